// round 2
// baseline (speedup 1.0000x reference)
#include <cuda_runtime.h>

#define BN   8
#define HH   720
#define WW   1280
#define NPIX (HH * WW)
#define TOT  (BN * NPIX)
#define NQUAD (TOT / 4)
#define SENT 0x7F7F7F7Fu   // 3.39e38f as float; > any depth, byte-uniform

// Scratch (allocation-free rule: __device__ globals)
__device__ unsigned int g_mind[TOT];
__device__ float        g_cnt [TOT];
__device__ float2       g_sum [TOT];   // interleaved (sumx, sumy)

// ---------------------------------------------------------------- init
__global__ __launch_bounds__(256)
void k_init() {
    int q = blockIdx.x * blockDim.x + threadIdx.x;
    if (q >= NQUAD) return;
    int i0 = q * 4;
    *(uint4*)(g_mind + i0) = make_uint4(SENT, SENT, SENT, SENT);
    *(float4*)(g_cnt + i0) = make_float4(0.f, 0.f, 0.f, 0.f);
    float4* sp = (float4*)(g_sum + i0);   // 2 float4 = 4 float2
    sp[0] = make_float4(0.f, 0.f, 0.f, 0.f);
    sp[1] = make_float4(0.f, 0.f, 0.f, 0.f);
}

// ---------------------------------------------------------------- min pass
__global__ __launch_bounds__(256)
void k_min(const float* __restrict__ flow, const float* __restrict__ depth) {
    int q = blockIdx.x * blockDim.x + threadIdx.x;
    if (q >= NQUAD) return;
    int i0 = q * 4;
    int b  = i0 / NPIX;
    int p0 = i0 - b * NPIX;
    int y  = p0 / WW;
    int x0 = p0 - y * WW;

    const float4 fx4 = *(const float4*)(flow  + (size_t)b * 2 * NPIX + p0);
    const float4 fy4 = *(const float4*)(flow  + (size_t)b * 2 * NPIX + NPIX + p0);
    const float4 d4  = *(const float4*)(depth + (size_t)b * NPIX + p0);

    float fx[4] = {fx4.x, fx4.y, fx4.z, fx4.w};
    float fy[4] = {fy4.x, fy4.y, fy4.z, fy4.w};
    float dd[4] = {d4.x,  d4.y,  d4.z,  d4.w};

    unsigned int* mbase = g_mind + (size_t)b * NPIX;
    float yf = (float)y;

#pragma unroll
    for (int j = 0; j < 4; j++) {
        float x2 = (float)(x0 + j) + fx[j];
        float y2 = yf + fy[j];
        if (x2 >= 0.0f && y2 >= 0.0f &&
            x2 <= (float)(WW - 1) && y2 <= (float)(HH - 1)) {
            int xL = min(max((int)floorf(x2), 0), WW - 1);
            int yT = min(max((int)floorf(y2), 0), HH - 1);
            int xR = min(xL + 1, WW - 1);
            int yB = min(yT + 1, HH - 1);
            unsigned int du = __float_as_uint(dd[j]);
            atomicMin(mbase + yT * WW + xL, du);
            atomicMin(mbase + yT * WW + xR, du);
            atomicMin(mbase + yB * WW + xL, du);
            atomicMin(mbase + yB * WW + xR, du);
        }
    }
}

// ---------------------------------------------------------------- select pass
__global__ __launch_bounds__(256)
void k_select(const float* __restrict__ flow, const float* __restrict__ depth) {
    int q = blockIdx.x * blockDim.x + threadIdx.x;
    if (q >= NQUAD) return;
    int i0 = q * 4;
    int b  = i0 / NPIX;
    int p0 = i0 - b * NPIX;
    int y  = p0 / WW;
    int x0 = p0 - y * WW;

    const float4 fx4 = *(const float4*)(flow  + (size_t)b * 2 * NPIX + p0);
    const float4 fy4 = *(const float4*)(flow  + (size_t)b * 2 * NPIX + NPIX + p0);
    const float4 d4  = *(const float4*)(depth + (size_t)b * NPIX + p0);

    float fx[4] = {fx4.x, fx4.y, fx4.z, fx4.w};
    float fy[4] = {fy4.x, fy4.y, fy4.z, fy4.w};
    float dd[4] = {d4.x,  d4.y,  d4.z,  d4.w};

    const unsigned int* mbase = g_mind + (size_t)b * NPIX;
    float2* sbase = g_sum + (size_t)b * NPIX;
    float*  cbase = g_cnt + (size_t)b * NPIX;
    float yf = (float)y;

#pragma unroll
    for (int j = 0; j < 4; j++) {
        float x2 = (float)(x0 + j) + fx[j];
        float y2 = yf + fy[j];
        if (x2 >= 0.0f && y2 >= 0.0f &&
            x2 <= (float)(WW - 1) && y2 <= (float)(HH - 1)) {
            int xL = min(max((int)floorf(x2), 0), WW - 1);
            int yT = min(max((int)floorf(y2), 0), HH - 1);
            int xR = min(xL + 1, WW - 1);
            int yB = min(yT + 1, HH - 1);
            unsigned int du = __float_as_uint(dd[j]);
            float nx = -fx[j], ny = -fy[j];
            int ts[4] = {yT * WW + xL, yT * WW + xR, yB * WW + xL, yB * WW + xR};
#pragma unroll
            for (int k = 0; k < 4; k++) {
                int t = ts[k];
                if (mbase[t] == du) {
                    asm volatile("red.global.add.v2.f32 [%0], {%1, %2};"
                                 :: "l"(sbase + t), "f"(nx), "f"(ny) : "memory");
                    atomicAdd(cbase + t, 1.0f);
                }
            }
        }
    }
}

// ---------------------------------------------------------------- normalize + write out
__global__ __launch_bounds__(256)
void k_norm(float* __restrict__ out) {
    int q = blockIdx.x * blockDim.x + threadIdx.x;
    if (q >= NQUAD) return;
    int i0 = q * 4;                 // global index == b*NPIX + p0
    int b  = i0 / NPIX;
    int p0 = i0 - b * NPIX;

    const float4* sp = (const float4*)(g_sum + i0);
    float4 s01 = sp[0];             // (x0,y0,x1,y1)
    float4 s23 = sp[1];             // (x2,y2,x3,y3)
    float4 c4  = *(const float4*)(g_cnt + i0);

    float4 ox, oy;
    ox.x = (c4.x > 0.0f) ? s01.x / c4.x : 0.0f;
    oy.x = (c4.x > 0.0f) ? s01.y / c4.x : 0.0f;
    ox.y = (c4.y > 0.0f) ? s01.z / c4.y : 0.0f;
    oy.y = (c4.y > 0.0f) ? s01.w / c4.y : 0.0f;
    ox.z = (c4.z > 0.0f) ? s23.x / c4.z : 0.0f;
    oy.z = (c4.z > 0.0f) ? s23.y / c4.z : 0.0f;
    ox.w = (c4.w > 0.0f) ? s23.z / c4.w : 0.0f;
    oy.w = (c4.w > 0.0f) ? s23.w / c4.w : 0.0f;

    *(float4*)(out + (size_t)b * 2 * NPIX + p0)        = ox;
    *(float4*)(out + (size_t)b * 2 * NPIX + NPIX + p0) = oy;
}

extern "C" void kernel_launch(void* const* d_in, const int* in_sizes, int n_in,
                              void* d_out, int out_size) {
    const float* flow  = (const float*)d_in[0];   // (B,2,H,W)
    const float* depth = (const float*)d_in[1];   // (B,1,H,W)
    float* out = (float*)d_out;                   // (B,2,H,W)

    const int threads = 256;
    const int blocks  = (NQUAD + threads - 1) / threads;   // 7200

    k_init  <<<blocks, threads>>>();
    k_min   <<<blocks, threads>>>(flow, depth);
    k_select<<<blocks, threads>>>(flow, depth);
    k_norm  <<<blocks, threads>>>(out);
}

// round 3
// speedup vs baseline: 1.1737x; 1.1737x over previous
#include <cuda_runtime.h>

#define BN   8
#define HH   720
#define WW   1280
#define NPIX (HH * WW)
#define TOT  (BN * NPIX)
#define NQUAD (TOT / 4)
#define SENT 0x7F7F7F7Fu   // 3.39e38f as float; > any depth, byte-uniform

// Scratch (allocation-free rule: __device__ globals)
__device__ unsigned int g_mind[TOT];
__device__ float4       g_acc [TOT];   // (sumx, sumy, cnt, pad)

// ---------------------------------------------------------------- init
__global__ __launch_bounds__(256)
void k_init() {
    int q = blockIdx.x * blockDim.x + threadIdx.x;
    if (q >= NQUAD) return;
    int i0 = q * 4;
    *(uint4*)(g_mind + i0) = make_uint4(SENT, SENT, SENT, SENT);
    float4 z = make_float4(0.f, 0.f, 0.f, 0.f);
    float4* ap = g_acc + i0;
    ap[0] = z; ap[1] = z; ap[2] = z; ap[3] = z;
}

// ---------------------------------------------------------------- min pass (1 px/thread)
__global__ __launch_bounds__(256)
void k_min(const float* __restrict__ flow, const float* __restrict__ depth) {
    int i = blockIdx.x * blockDim.x + threadIdx.x;
    if (i >= TOT) return;
    int b = i / NPIX;
    int p = i - b * NPIX;
    int y = p / WW;
    int x = p - y * WW;

    float fx = flow[(size_t)b * 2 * NPIX + p];
    float fy = flow[(size_t)b * 2 * NPIX + NPIX + p];
    float x2 = (float)x + fx;
    float y2 = (float)y + fy;
    if (!(x2 >= 0.0f && y2 >= 0.0f &&
          x2 <= (float)(WW - 1) && y2 <= (float)(HH - 1))) return;

    int xL = min(max((int)floorf(x2), 0), WW - 1);
    int yT = min(max((int)floorf(y2), 0), HH - 1);
    int xR = min(xL + 1, WW - 1);
    int yB = min(yT + 1, HH - 1);

    unsigned int du = __float_as_uint(depth[(size_t)b * NPIX + p]);
    unsigned int* mbase = g_mind + (size_t)b * NPIX;
    atomicMin(mbase + yT * WW + xL, du);
    atomicMin(mbase + yT * WW + xR, du);
    atomicMin(mbase + yB * WW + xL, du);
    atomicMin(mbase + yB * WW + xR, du);
}

// ---------------------------------------------------------------- select pass (1 px/thread)
__global__ __launch_bounds__(256)
void k_select(const float* __restrict__ flow, const float* __restrict__ depth) {
    int i = blockIdx.x * blockDim.x + threadIdx.x;
    if (i >= TOT) return;
    int b = i / NPIX;
    int p = i - b * NPIX;
    int y = p / WW;
    int x = p - y * WW;

    float fx = flow[(size_t)b * 2 * NPIX + p];
    float fy = flow[(size_t)b * 2 * NPIX + NPIX + p];
    float x2 = (float)x + fx;
    float y2 = (float)y + fy;
    if (!(x2 >= 0.0f && y2 >= 0.0f &&
          x2 <= (float)(WW - 1) && y2 <= (float)(HH - 1))) return;

    int xL = min(max((int)floorf(x2), 0), WW - 1);
    int yT = min(max((int)floorf(y2), 0), HH - 1);
    int xR = min(xL + 1, WW - 1);
    int yB = min(yT + 1, HH - 1);

    unsigned int du = __float_as_uint(depth[(size_t)b * NPIX + p]);
    const unsigned int* mbase = g_mind + (size_t)b * NPIX;
    float4* abase = g_acc + (size_t)b * NPIX;
    float nx = -fx, ny = -fy;

    int ts[4] = {yT * WW + xL, yT * WW + xR, yB * WW + xL, yB * WW + xR};
#pragma unroll
    for (int k = 0; k < 4; k++) {
        int t = ts[k];
        if (mbase[t] == du) {
            asm volatile("red.global.add.v4.f32 [%0], {%1, %2, %3, %4};"
                         :: "l"(abase + t), "f"(nx), "f"(ny), "f"(1.0f), "f"(0.0f)
                         : "memory");
        }
    }
}

// ---------------------------------------------------------------- normalize + write out (quad/thread)
__global__ __launch_bounds__(256)
void k_norm(float* __restrict__ out) {
    int q = blockIdx.x * blockDim.x + threadIdx.x;
    if (q >= NQUAD) return;
    int i0 = q * 4;                 // == b*NPIX + p0
    int b  = i0 / NPIX;
    int p0 = i0 - b * NPIX;

    const float4* ap = g_acc + i0;
    float4 a0 = ap[0], a1 = ap[1], a2 = ap[2], a3 = ap[3];

    float4 ox, oy;
    ox.x = (a0.z > 0.0f) ? a0.x / a0.z : 0.0f;
    oy.x = (a0.z > 0.0f) ? a0.y / a0.z : 0.0f;
    ox.y = (a1.z > 0.0f) ? a1.x / a1.z : 0.0f;
    oy.y = (a1.z > 0.0f) ? a1.y / a1.z : 0.0f;
    ox.z = (a2.z > 0.0f) ? a2.x / a2.z : 0.0f;
    oy.z = (a2.z > 0.0f) ? a2.y / a2.z : 0.0f;
    ox.w = (a3.z > 0.0f) ? a3.x / a3.z : 0.0f;
    oy.w = (a3.z > 0.0f) ? a3.y / a3.z : 0.0f;

    *(float4*)(out + (size_t)b * 2 * NPIX + p0)        = ox;
    *(float4*)(out + (size_t)b * 2 * NPIX + NPIX + p0) = oy;
}

extern "C" void kernel_launch(void* const* d_in, const int* in_sizes, int n_in,
                              void* d_out, int out_size) {
    const float* flow  = (const float*)d_in[0];   // (B,2,H,W)
    const float* depth = (const float*)d_in[1];   // (B,1,H,W)
    float* out = (float*)d_out;                   // (B,2,H,W)

    const int threads  = 256;
    const int blocksPx = (TOT + threads - 1) / threads;     // 28800
    const int blocksQd = (NQUAD + threads - 1) / threads;   // 7200

    k_init  <<<blocksQd, threads>>>();
    k_min   <<<blocksPx, threads>>>(flow, depth);
    k_select<<<blocksPx, threads>>>(flow, depth);
    k_norm  <<<blocksQd, threads>>>(out);
}

// round 4
// speedup vs baseline: 1.2121x; 1.0327x over previous
#include <cuda_runtime.h>

#define BN   8
#define HH   720
#define WW   1280
#define NPIX (HH * WW)
#define TOT  (BN * NPIX)
#define NQUAD (TOT / 4)
#define SENT 0x7F7F7F7Fu   // 3.39e38f as float; > any depth, byte-uniform

// Scratch (allocation-free rule: __device__ globals)
__device__ unsigned int g_mind[TOT];
__device__ float4       g_acc [TOT];   // (sumx, sumy, cnt, pad)

// ---------------------------------------------------------------- init
__global__ __launch_bounds__(256)
void k_init() {
    int q = blockIdx.x * blockDim.x + threadIdx.x;   // exact: NQUAD % 256 == 0
    int i0 = q * 4;
    *(uint4*)(g_mind + i0) = make_uint4(SENT, SENT, SENT, SENT);
    float4 z = make_float4(0.f, 0.f, 0.f, 0.f);
    float4* ap = g_acc + i0;
    ap[0] = z; ap[1] = z; ap[2] = z; ap[3] = z;
}

// ---------------------------------------------------------------- min pass (1 px/thread, PDL over init)
__global__ __launch_bounds__(256)
void k_min(const float* __restrict__ flow, const float* __restrict__ depth) {
    int i = blockIdx.x * blockDim.x + threadIdx.x;   // exact: TOT % 256 == 0
    int b = i / NPIX;
    int p = i - b * NPIX;
    int y = p / WW;
    int x = p - y * WW;

    // Front-end: independent of init's writes (flow/depth only)
    float fx = flow[(size_t)b * 2 * NPIX + p];
    float fy = flow[(size_t)b * 2 * NPIX + NPIX + p];
    float du_f = depth[(size_t)b * NPIX + p];
    float x2 = (float)x + fx;
    float y2 = (float)y + fy;
    bool valid = (x2 >= 0.0f && y2 >= 0.0f &&
                  x2 <= (float)(WW - 1) && y2 <= (float)(HH - 1));

    int xL = min(max((int)floorf(x2), 0), WW - 1);
    int yT = min(max((int)floorf(y2), 0), HH - 1);
    int xR = min(xL + 1, WW - 1);
    int yB = min(yT + 1, HH - 1);

    // Wait for k_init's writes to g_mind to be visible
    cudaGridDependencySynchronize();

    if (valid) {
        unsigned int du = __float_as_uint(du_f);
        unsigned int* mbase = g_mind + (size_t)b * NPIX;
        atomicMin(mbase + yT * WW + xL, du);
        atomicMin(mbase + yT * WW + xR, du);
        atomicMin(mbase + yB * WW + xL, du);
        atomicMin(mbase + yB * WW + xR, du);
    }
    cudaTriggerProgrammaticLaunchCompletion();
}

// ---------------------------------------------------------------- select pass (1 px/thread, PDL over min)
__global__ __launch_bounds__(256)
void k_select(const float* __restrict__ flow, const float* __restrict__ depth) {
    int i = blockIdx.x * blockDim.x + threadIdx.x;
    int b = i / NPIX;
    int p = i - b * NPIX;
    int y = p / WW;
    int x = p - y * WW;

    // Front-end: flow/depth loads + target math overlap k_min's atomic tail
    float fx = flow[(size_t)b * 2 * NPIX + p];
    float fy = flow[(size_t)b * 2 * NPIX + NPIX + p];
    float du_f = depth[(size_t)b * NPIX + p];
    float x2 = (float)x + fx;
    float y2 = (float)y + fy;
    bool valid = (x2 >= 0.0f && y2 >= 0.0f &&
                  x2 <= (float)(WW - 1) && y2 <= (float)(HH - 1));

    int xL = min(max((int)floorf(x2), 0), WW - 1);
    int yT = min(max((int)floorf(y2), 0), HH - 1);
    int xR = min(xL + 1, WW - 1);
    int yB = min(yT + 1, HH - 1);
    int ts[4] = {yT * WW + xL, yT * WW + xR, yB * WW + xL, yB * WW + xR};

    // Wait for all of k_min's atomicMin results
    cudaGridDependencySynchronize();

    if (valid) {
        unsigned int du = __float_as_uint(du_f);
        const unsigned int* mbase = g_mind + (size_t)b * NPIX;
        float4* abase = g_acc + (size_t)b * NPIX;
        float nx = -fx, ny = -fy;
#pragma unroll
        for (int k = 0; k < 4; k++) {
            int t = ts[k];
            if (mbase[t] == du) {
                asm volatile("red.global.add.v4.f32 [%0], {%1, %2, %3, %4};"
                             :: "l"(abase + t), "f"(nx), "f"(ny), "f"(1.0f), "f"(0.0f)
                             : "memory");
            }
        }
    }
    cudaTriggerProgrammaticLaunchCompletion();
}

// ---------------------------------------------------------------- normalize + write out (quad/thread, PDL over select)
__global__ __launch_bounds__(256)
void k_norm(float* __restrict__ out) {
    int q = blockIdx.x * blockDim.x + threadIdx.x;
    int i0 = q * 4;                 // == b*NPIX + p0
    int b  = i0 / NPIX;
    int p0 = i0 - b * NPIX;
    float* ox_p = out + (size_t)b * 2 * NPIX + p0;
    float* oy_p = ox_p + NPIX;

    cudaGridDependencySynchronize();

    const float4* ap = g_acc + i0;
    float4 a0 = ap[0], a1 = ap[1], a2 = ap[2], a3 = ap[3];

    float4 ox, oy;
    ox.x = (a0.z > 0.0f) ? a0.x / a0.z : 0.0f;
    oy.x = (a0.z > 0.0f) ? a0.y / a0.z : 0.0f;
    ox.y = (a1.z > 0.0f) ? a1.x / a1.z : 0.0f;
    oy.y = (a1.z > 0.0f) ? a1.y / a1.z : 0.0f;
    ox.z = (a2.z > 0.0f) ? a2.x / a2.z : 0.0f;
    oy.z = (a2.z > 0.0f) ? a2.y / a2.z : 0.0f;
    ox.w = (a3.z > 0.0f) ? a3.x / a3.z : 0.0f;
    oy.w = (a3.z > 0.0f) ? a3.y / a3.z : 0.0f;

    *(float4*)ox_p = ox;
    *(float4*)oy_p = oy;
}

// ---------------------------------------------------------------- host
static inline void launch_ex(const void* fn, int blocks, void** args, bool pdl) {
    cudaLaunchConfig_t cfg = {};
    cfg.gridDim  = dim3(blocks, 1, 1);
    cfg.blockDim = dim3(256, 1, 1);
    cfg.stream   = 0;   // same stream <<<>>> used in prior (passing) rounds
    cudaLaunchAttribute attr[1];
    if (pdl) {
        attr[0].id = cudaLaunchAttributeProgrammaticStreamSerialization;
        attr[0].val.programmaticStreamSerializationAllowed = 1;
        cfg.attrs = attr;
        cfg.numAttrs = 1;
    }
    cudaLaunchKernelExC(&cfg, fn, args);
}

extern "C" void kernel_launch(void* const* d_in, const int* in_sizes, int n_in,
                              void* d_out, int out_size) {
    const float* flow  = (const float*)d_in[0];   // (B,2,H,W)
    const float* depth = (const float*)d_in[1];   // (B,1,H,W)
    float* out = (float*)d_out;                   // (B,2,H,W)

    const int blocksPx = TOT / 256;     // 28800 (exact)
    const int blocksQd = NQUAD / 256;   // 7200  (exact)

    void* args_none[] = { nullptr };
    void* args_md[]   = { (void*)&flow, (void*)&depth };
    void* args_out[]  = { (void*)&out };

    launch_ex((const void*)k_init,   blocksQd, args_none, false);
    launch_ex((const void*)k_min,    blocksPx, args_md,   true);
    launch_ex((const void*)k_select, blocksPx, args_md,   true);
    launch_ex((const void*)k_norm,   blocksQd, args_out,  true);
}